// round 2
// baseline (speedup 1.0000x reference)
#include <cuda_runtime.h>
#include <math.h>

// Problem constants
#define BS      2
#define SEQ     2048
#define DMODEL  1024
#define HEADS   16
#define DK      64
#define MROWS   (BS * SEQ)          // 4096
#define QKV_ELEMS (BS * HEADS * SEQ * DK)  // 4,194,304

// Scratch (allocation-free rule: __device__ globals)
__device__ float g_Q[QKV_ELEMS];
__device__ float g_K[QKV_ELEMS];
__device__ float g_V[QKV_ELEMS];

// ---------------------------------------------------------------------------
// Tiled GEMM:  Y[m,n] = sum_k A[m,k] * W[n,k] + bias[n]
// mode 0: A = [M,K] row-major input,  C written to head-split [b,h,s,d] scratch
// mode 1: A = scores in [b,h,s,d] layout (index-remapped), C = [M,N] row-major + bias
// BM=BN=64, BK=16, 256 threads, 4x4 micro-tile.
// ---------------------------------------------------------------------------
__global__ __launch_bounds__(256) void mha_gemm_kernel(
    const float* __restrict__ A, const float* __restrict__ W,
    const float* __restrict__ bias, float* __restrict__ C, int mode)
{
    const int K = DMODEL;
    __shared__ float As[16 * 64];   // As[kk][m]
    __shared__ float Bs[16 * 64];   // Bs[kk][n]

    const int tid = threadIdx.x;
    const int tx = tid & 15;        // 0..15 -> n micro
    const int ty = tid >> 4;        // 0..15 -> m micro
    const int m0 = blockIdx.y * 64;
    const int n0 = blockIdx.x * 64;

    const int ld_row = tid >> 2;    // 0..63
    const int ld_quad = tid & 3;    // 0..3  (float4 within 16-wide k slab)

    float acc[4][4];
#pragma unroll
    for (int i = 0; i < 4; i++)
#pragma unroll
        for (int j = 0; j < 4; j++) acc[i][j] = 0.f;

    for (int k0 = 0; k0 < K; k0 += 16) {
        // --- load A slab (64 rows x 16 k) ---
        float4 a4;
        {
            int m = m0 + ld_row;
            int k = k0 + ld_quad * 4;
            const float* src;
            if (mode == 0) {
                src = A + (size_t)m * K + k;
            } else {
                int b = m >> 11, s = m & 2047;
                int h = k >> 6, d = k & 63;
                src = A + (size_t)(((b * HEADS + h) * SEQ) + s) * DK + d;
            }
            a4 = *reinterpret_cast<const float4*>(src);
        }
        As[(ld_quad * 4 + 0) * 64 + ld_row] = a4.x;
        As[(ld_quad * 4 + 1) * 64 + ld_row] = a4.y;
        As[(ld_quad * 4 + 2) * 64 + ld_row] = a4.z;
        As[(ld_quad * 4 + 3) * 64 + ld_row] = a4.w;

        // --- load B slab (64 n-rows of W, 16 k) ---
        {
            int n = n0 + ld_row;
            int k = k0 + ld_quad * 4;
            float4 b4 = *reinterpret_cast<const float4*>(W + (size_t)n * K + k);
            Bs[(ld_quad * 4 + 0) * 64 + ld_row] = b4.x;
            Bs[(ld_quad * 4 + 1) * 64 + ld_row] = b4.y;
            Bs[(ld_quad * 4 + 2) * 64 + ld_row] = b4.z;
            Bs[(ld_quad * 4 + 3) * 64 + ld_row] = b4.w;
        }
        __syncthreads();

#pragma unroll
        for (int kk = 0; kk < 16; kk++) {
            float4 av = *reinterpret_cast<const float4*>(&As[kk * 64 + ty * 4]);
            float4 bv = *reinterpret_cast<const float4*>(&Bs[kk * 64 + tx * 4]);
            float a[4] = {av.x, av.y, av.z, av.w};
            float b[4] = {bv.x, bv.y, bv.z, bv.w};
#pragma unroll
            for (int i = 0; i < 4; i++)
#pragma unroll
                for (int j = 0; j < 4; j++) acc[i][j] = fmaf(a[i], b[j], acc[i][j]);
        }
        __syncthreads();
    }

    // --- store ---
    if (mode == 0) {
        // head-split layout [b,h,s,d]
#pragma unroll
        for (int i = 0; i < 4; i++) {
            int m = m0 + ty * 4 + i;
            int b = m >> 11, s = m & 2047;
            int n = n0 + tx * 4;
            int h = n >> 6, d = n & 63;
            float4 v = make_float4(acc[i][0], acc[i][1], acc[i][2], acc[i][3]);
            *reinterpret_cast<float4*>(
                C + (size_t)(((b * HEADS + h) * SEQ) + s) * DK + d) = v;
        }
    } else {
        float4 bv = *reinterpret_cast<const float4*>(bias + n0 + tx * 4);
#pragma unroll
        for (int i = 0; i < 4; i++) {
            int m = m0 + ty * 4 + i;
            float4 v = make_float4(acc[i][0] + bv.x, acc[i][1] + bv.y,
                                   acc[i][2] + bv.z, acc[i][3] + bv.w);
            *reinterpret_cast<float4*>(C + (size_t)m * DMODEL + n0 + tx * 4) = v;
        }
    }
}

// ---------------------------------------------------------------------------
// Flash attention (fp32): one CTA per (bh, 64-row Q tile).
// smem: Qs[d][r], Ks[d][c] (transposed), Vs[j][d] (natural), Ps[r][c] (natural)
// ---------------------------------------------------------------------------
__device__ __forceinline__ float red_max16(float v) {
#pragma unroll
    for (int m = 8; m > 0; m >>= 1) v = fmaxf(v, __shfl_xor_sync(0xffffffffu, v, m));
    return v;
}
__device__ __forceinline__ float red_sum16(float v) {
#pragma unroll
    for (int m = 8; m > 0; m >>= 1) v += __shfl_xor_sync(0xffffffffu, v, m);
    return v;
}

extern __shared__ float smem[];

__global__ __launch_bounds__(256) void mha_attn_kernel(float* __restrict__ scores_out)
{
    float* Qs = smem;           // 4096 floats  [d*64 + r]
    float* Ks = smem + 4096;    // 4096 floats  [d*64 + c]
    float* Vs = smem + 8192;    // 4096 floats  [j*64 + d]
    float* Ps = smem + 12288;   // 4096 floats  [r*64 + c]

    const int tid = threadIdx.x;
    const int tx = tid & 15;
    const int ty = tid >> 4;
    const int q0 = blockIdx.x * 64;
    const int bh = blockIdx.y;

    const float* Qb = g_Q + (size_t)bh * SEQ * DK;
    const float* Kb = g_K + (size_t)bh * SEQ * DK;
    const float* Vb = g_V + (size_t)bh * SEQ * DK;

    const float qscale = 0.125f;  // 1/sqrt(64)

    // load Q tile (transpose into [d][r]), folding in softmax scale
#pragma unroll
    for (int it = 0; it < 4; it++) {
        int idx = tid + it * 256;           // 0..1023
        int r = idx >> 4;
        int d = (idx & 15) * 4;
        float4 v = *reinterpret_cast<const float4*>(Qb + (size_t)(q0 + r) * DK + d);
        Qs[(d + 0) * 64 + r] = v.x * qscale;
        Qs[(d + 1) * 64 + r] = v.y * qscale;
        Qs[(d + 2) * 64 + r] = v.z * qscale;
        Qs[(d + 3) * 64 + r] = v.w * qscale;
    }

    float m_i[4], l_i[4], o[4][4];
#pragma unroll
    for (int i = 0; i < 4; i++) {
        m_i[i] = -INFINITY; l_i[i] = 0.f;
#pragma unroll
        for (int j = 0; j < 4; j++) o[i][j] = 0.f;
    }
    __syncthreads();

    for (int kt = 0; kt < SEQ / 64; kt++) {
        const int c0 = kt * 64;
        // load K tile transposed, V tile natural
#pragma unroll
        for (int it = 0; it < 4; it++) {
            int idx = tid + it * 256;
            int r = idx >> 4;
            int d = (idx & 15) * 4;
            float4 kv = *reinterpret_cast<const float4*>(Kb + (size_t)(c0 + r) * DK + d);
            Ks[(d + 0) * 64 + r] = kv.x;
            Ks[(d + 1) * 64 + r] = kv.y;
            Ks[(d + 2) * 64 + r] = kv.z;
            Ks[(d + 3) * 64 + r] = kv.w;
            float4 vv = *reinterpret_cast<const float4*>(Vb + (size_t)(c0 + r) * DK + d);
            *reinterpret_cast<float4*>(&Vs[r * 64 + d]) = vv;
        }
        __syncthreads();

        // S = (Q*scale) K^T   (4x4 per thread)
        float s[4][4];
#pragma unroll
        for (int i = 0; i < 4; i++)
#pragma unroll
            for (int j = 0; j < 4; j++) s[i][j] = 0.f;
#pragma unroll 8
        for (int d = 0; d < 64; d++) {
            float4 qv = *reinterpret_cast<const float4*>(&Qs[d * 64 + ty * 4]);
            float4 kv = *reinterpret_cast<const float4*>(&Ks[d * 64 + tx * 4]);
            float a[4] = {qv.x, qv.y, qv.z, qv.w};
            float b[4] = {kv.x, kv.y, kv.z, kv.w};
#pragma unroll
            for (int i = 0; i < 4; i++)
#pragma unroll
                for (int j = 0; j < 4; j++) s[i][j] = fmaf(a[i], b[j], s[i][j]);
        }

        // online softmax update (per row)
        float p[4][4];
#pragma unroll
        for (int i = 0; i < 4; i++) {
            float tm = fmaxf(fmaxf(s[i][0], s[i][1]), fmaxf(s[i][2], s[i][3]));
            tm = red_max16(tm);
            float m_new = fmaxf(m_i[i], tm);
            float rs = 0.f;
#pragma unroll
            for (int j = 0; j < 4; j++) { p[i][j] = __expf(s[i][j] - m_new); rs += p[i][j]; }
            rs = red_sum16(rs);
            float sc = __expf(m_i[i] - m_new);
            l_i[i] = l_i[i] * sc + rs;
            m_i[i] = m_new;
#pragma unroll
            for (int j = 0; j < 4; j++) o[i][j] *= sc;
        }
        __syncthreads();   // all reads of Ks done; safe to publish P

#pragma unroll
        for (int i = 0; i < 4; i++) {
            *reinterpret_cast<float4*>(&Ps[(ty * 4 + i) * 64 + tx * 4]) =
                make_float4(p[i][0], p[i][1], p[i][2], p[i][3]);
        }
        __syncthreads();

        // O += P @ V
#pragma unroll 8
        for (int j = 0; j < 64; j++) {
            float4 vv = *reinterpret_cast<const float4*>(&Vs[j * 64 + tx * 4]);
            float pv[4];
#pragma unroll
            for (int i = 0; i < 4; i++) pv[i] = Ps[(ty * 4 + i) * 64 + j];
#pragma unroll
            for (int i = 0; i < 4; i++) {
                o[i][0] = fmaf(pv[i], vv.x, o[i][0]);
                o[i][1] = fmaf(pv[i], vv.y, o[i][1]);
                o[i][2] = fmaf(pv[i], vv.z, o[i][2]);
                o[i][3] = fmaf(pv[i], vv.w, o[i][3]);
            }
        }
        __syncthreads();   // done with Vs/Ps before next tile load
    }

    // normalize and write scores [b,h,s,d]
#pragma unroll
    for (int i = 0; i < 4; i++) {
        float inv = 1.f / l_i[i];
        int r = q0 + ty * 4 + i;
        float4 v = make_float4(o[i][0] * inv, o[i][1] * inv, o[i][2] * inv, o[i][3] * inv);
        *reinterpret_cast<float4*>(scores_out + ((size_t)bh * SEQ + r) * DK + tx * 4) = v;
    }
}

// ---------------------------------------------------------------------------
extern "C" void kernel_launch(void* const* d_in, const int* in_sizes, int n_in,
                              void* d_out, int out_size)
{
    const float* query = (const float*)d_in[0];
    const float* key   = (const float*)d_in[1];
    const float* value = (const float*)d_in[2];
    const float* Wq = (const float*)d_in[3];
    const float* bq = (const float*)d_in[4];
    const float* Wk = (const float*)d_in[5];
    const float* bk = (const float*)d_in[6];
    const float* Wv = (const float*)d_in[7];
    const float* bv = (const float*)d_in[8];
    const float* Wo = (const float*)d_in[9];
    const float* bo = (const float*)d_in[10];

    float* out    = (float*)d_out;                 // [bs, seq, d_model]
    float* scores = (float*)d_out + QKV_ELEMS;     // [bs, h, seq, d_k]

    float *dQ, *dK, *dV;
    cudaGetSymbolAddress((void**)&dQ, g_Q);
    cudaGetSymbolAddress((void**)&dK, g_K);
    cudaGetSymbolAddress((void**)&dV, g_V);

    dim3 ggrid(DMODEL / 64, MROWS / 64);   // (16, 64)
    mha_gemm_kernel<<<ggrid, 256>>>(query, Wq, bq, dQ, 0);
    mha_gemm_kernel<<<ggrid, 256>>>(key,   Wk, bk, dK, 0);
    mha_gemm_kernel<<<ggrid, 256>>>(value, Wv, bv, dV, 0);

    static bool attr_set = false;
    if (!attr_set) {
        cudaFuncSetAttribute(mha_attn_kernel,
                             cudaFuncAttributeMaxDynamicSharedMemorySize, 16384 * 4);
        attr_set = true;
    }
    dim3 agrid(SEQ / 64, BS * HEADS);      // (32, 32)
    mha_attn_kernel<<<agrid, 256, 16384 * 4>>>(scores);

    mha_gemm_kernel<<<ggrid, 256>>>(scores, Wo, bo, out, 1);
}

// round 6
// speedup vs baseline: 1.4860x; 1.4860x over previous
#include <cuda_runtime.h>
#include <cuda_bf16.h>
#include <math.h>
#include <stdint.h>

// Problem constants
#define BS      2
#define SEQ     2048
#define DMODEL  1024
#define HEADS   16
#define DK      64
#define MROWS   (BS * SEQ)                  // 4096
#define QKV_ELEMS (BS * HEADS * SEQ * DK)   // 4,194,304

// ---------------------------------------------------------------------------
// Device scratch (allocation-free rule)
// ---------------------------------------------------------------------------
__device__ float g_Q[QKV_ELEMS];
__device__ float g_K[QKV_ELEMS];
__device__ float g_V[QKV_ELEMS];
__device__ __align__(16) __nv_bfloat16 g_Ah[MROWS * DMODEL];
__device__ __align__(16) __nv_bfloat16 g_Al[MROWS * DMODEL];
__device__ __align__(16) __nv_bfloat16 g_Wh[DMODEL * DMODEL];
__device__ __align__(16) __nv_bfloat16 g_Wl[DMODEL * DMODEL];

// ---------------------------------------------------------------------------
// Helpers
// ---------------------------------------------------------------------------
__device__ __forceinline__ uint32_t smem_u32(const void* p) {
    uint32_t a;
    asm("{ .reg .u64 t; cvta.to.shared.u64 t, %1; cvt.u32.u64 %0, t; }" : "=r"(a) : "l"(p));
    return a;
}
__device__ __forceinline__ uint32_t lds32(uint32_t addr) {
    uint32_t v;
    asm volatile("ld.shared.b32 %0, [%1];" : "=r"(v) : "r"(addr));
    return v;
}
__device__ __forceinline__ void cp_async16(uint32_t saddr, const void* gaddr) {
    asm volatile("cp.async.cg.shared.global [%0], [%1], 16;" :: "r"(saddr), "l"(gaddr));
}
#define CP_COMMIT() asm volatile("cp.async.commit_group;" ::: "memory")
#define CP_WAIT(n)  asm volatile("cp.async.wait_group %0;" :: "n"(n) : "memory")

// D = A(16x16) * B(16x8) + D, bf16 inputs, fp32 accum
__device__ __forceinline__ void mma16816(float* c, const uint32_t* a, const uint32_t* b) {
    asm volatile(
        "mma.sync.aligned.m16n8k16.row.col.f32.bf16.bf16.f32 "
        "{%0,%1,%2,%3}, {%4,%5,%6,%7}, {%8,%9}, {%0,%1,%2,%3};"
        : "+f"(c[0]), "+f"(c[1]), "+f"(c[2]), "+f"(c[3])
        : "r"(a[0]), "r"(a[1]), "r"(a[2]), "r"(a[3]), "r"(b[0]), "r"(b[1]));
}

// ---------------------------------------------------------------------------
// fp32 -> bf16 hi/lo split. remap=1: src is scores [b,h,s,d] gathered as [m,k]
// ---------------------------------------------------------------------------
__global__ __launch_bounds__(256) void split_kernel(
    const float* __restrict__ src, __nv_bfloat16* __restrict__ hi,
    __nv_bfloat16* __restrict__ lo, int n4, int remap)
{
    int i = blockIdx.x * blockDim.x + threadIdx.x;
    if (i >= n4) return;
    int e = i * 4;
    const float4* sp;
    if (!remap) {
        sp = reinterpret_cast<const float4*>(src) + i;
    } else {
        int m = e >> 10, k = e & 1023;
        int b = m >> 11, s = m & 2047, h = k >> 6, d = k & 63;
        sp = reinterpret_cast<const float4*>(
            src + (size_t)((b * HEADS + h) * SEQ + s) * DK + d);
    }
    float4 f = *sp;
    __nv_bfloat16 h0 = __float2bfloat16(f.x), h1 = __float2bfloat16(f.y);
    __nv_bfloat16 h2 = __float2bfloat16(f.z), h3 = __float2bfloat16(f.w);
    __nv_bfloat16 l0 = __float2bfloat16(f.x - __bfloat162float(h0));
    __nv_bfloat16 l1 = __float2bfloat16(f.y - __bfloat162float(h1));
    __nv_bfloat16 l2 = __float2bfloat16(f.z - __bfloat162float(h2));
    __nv_bfloat16 l3 = __float2bfloat16(f.w - __bfloat162float(h3));
    __nv_bfloat162 hp0 = __halves2bfloat162(h0, h1), hp1 = __halves2bfloat162(h2, h3);
    __nv_bfloat162 lp0 = __halves2bfloat162(l0, l1), lp1 = __halves2bfloat162(l2, l3);
    uint2 hv, lv;
    hv.x = *reinterpret_cast<uint32_t*>(&hp0); hv.y = *reinterpret_cast<uint32_t*>(&hp1);
    lv.x = *reinterpret_cast<uint32_t*>(&lp0); lv.y = *reinterpret_cast<uint32_t*>(&lp1);
    *reinterpret_cast<uint2*>(hi + e) = hv;
    *reinterpret_cast<uint2*>(lo + e) = lv;
}

// ---------------------------------------------------------------------------
// mma.sync bf16-split GEMM:  C[m,n] = sum_k A[m,k] W[n,k] + bias[n]
//   = Ah·Wh + Ah·Wl + Al·Wh  (fp32 accumulation in registers)
// CTA 128x128, BK=32, 256 threads, warps 2(M)x4(N), warp tile 64x32.
// Double-buffered cp.async smem; padded stride 40 bf16 = bank-conflict-free.
// mode 0: C written head-split [b,h,s,d].  mode 1: C row-major [m,n].
// ---------------------------------------------------------------------------
#define SA        40                     // smem row stride (bf16 elems)
#define TILE_B    (128 * SA * 2)         // 10240 bytes per tile
#define BUF_B     (4 * TILE_B)           // Ah|Al|Bh|Bl
#define GEMM_SMEM (2 * BUF_B)            // 81920 bytes

__global__ __launch_bounds__(256) void gemm_mma_kernel(
    const __nv_bfloat16* __restrict__ Ah, const __nv_bfloat16* __restrict__ Al,
    const __nv_bfloat16* __restrict__ Wh, const __nv_bfloat16* __restrict__ Wl,
    const float* __restrict__ bias, float* __restrict__ C, int mode)
{
    extern __shared__ __align__(128) char smem[];
    const uint32_t sb = smem_u32(smem);

    const int tid  = threadIdx.x;
    const int lane = tid & 31;
    const int wid  = tid >> 5;
    const int wm   = wid >> 2;          // 0..1
    const int wn   = wid & 3;           // 0..3
    const int g    = lane >> 2;         // 0..7
    const int t4   = lane & 3;          // 0..3

    const int m0 = blockIdx.y * 128;
    const int n0 = blockIdx.x * 128;

    // load indices: i = tid + it*256 -> r = i>>2 (0..127), c = i&3 (8-elem chunk)
    const int lr0 = tid >> 2;
    const int lc0 = (tid & 3) * 8;

    float acc[4][4][4];
#pragma unroll
    for (int mt = 0; mt < 4; mt++)
#pragma unroll
        for (int nt = 0; nt < 4; nt++)
#pragma unroll
            for (int q = 0; q < 4; q++) acc[mt][nt][q] = 0.f;

    // issue async loads of one k-tile into buffer `buf`
    auto load_tile = [&](int buf, int k0) {
        uint32_t base = sb + buf * BUF_B;
#pragma unroll
        for (int it = 0; it < 2; it++) {
            int r = lr0 + it * 64;
            uint32_t soff = (uint32_t)(r * SA + lc0) * 2;
            size_t ga = (size_t)(m0 + r) * DMODEL + k0 + lc0;
            size_t gb = (size_t)(n0 + r) * DMODEL + k0 + lc0;
            cp_async16(base + 0 * TILE_B + soff, Ah + ga);
            cp_async16(base + 1 * TILE_B + soff, Al + ga);
            cp_async16(base + 2 * TILE_B + soff, Wh + gb);
            cp_async16(base + 3 * TILE_B + soff, Wl + gb);
        }
        CP_COMMIT();
    };

    load_tile(0, 0);

    const int NT = DMODEL / 32;   // 32 k-tiles
    for (int kt = 0; kt < NT; kt++) {
        const int buf = kt & 1;
        if (kt + 1 < NT) {
            load_tile(buf ^ 1, (kt + 1) * 32);
            CP_WAIT(1);
        } else {
            CP_WAIT(0);
        }
        __syncthreads();

        const uint32_t bA = sb + buf * BUF_B;
        const uint32_t bB = bA + 2 * TILE_B;

#pragma unroll
        for (int s = 0; s < 2; s++) {
            const int kc = s * 16 + t4 * 2;
            uint32_t ah[4][4], al[4][4];
#pragma unroll
            for (int mt = 0; mt < 4; mt++) {
                int row = wm * 64 + mt * 16 + g;
                uint32_t o00 = (uint32_t)(row * SA + kc) * 2;
                uint32_t o10 = o00 + 8 * SA * 2;
                ah[mt][0] = lds32(bA + o00);
                ah[mt][1] = lds32(bA + o10);
                ah[mt][2] = lds32(bA + o00 + 16);
                ah[mt][3] = lds32(bA + o10 + 16);
                al[mt][0] = lds32(bA + TILE_B + o00);
                al[mt][1] = lds32(bA + TILE_B + o10);
                al[mt][2] = lds32(bA + TILE_B + o00 + 16);
                al[mt][3] = lds32(bA + TILE_B + o10 + 16);
            }
            uint32_t bh[4][2], bl[4][2];
#pragma unroll
            for (int nt = 0; nt < 4; nt++) {
                int n = wn * 32 + nt * 8 + g;
                uint32_t o = (uint32_t)(n * SA + kc) * 2;
                bh[nt][0] = lds32(bB + o);
                bh[nt][1] = lds32(bB + o + 16);
                bl[nt][0] = lds32(bB + TILE_B + o);
                bl[nt][1] = lds32(bB + TILE_B + o + 16);
            }
#pragma unroll
            for (int mt = 0; mt < 4; mt++)
#pragma unroll
                for (int nt = 0; nt < 4; nt++) {
                    mma16816(acc[mt][nt], ah[mt], bh[nt]);
                    mma16816(acc[mt][nt], ah[mt], bl[nt]);
                    mma16816(acc[mt][nt], al[mt], bh[nt]);
                }
        }
        __syncthreads();
    }

    // epilogue: C fragment c0,c1 -> (row,g col t4*2..+1), c2,c3 -> row+8
#pragma unroll
    for (int mt = 0; mt < 4; mt++) {
        int row0 = m0 + wm * 64 + mt * 16 + g;
#pragma unroll
        for (int nt = 0; nt < 4; nt++) {
            int col = n0 + wn * 32 + nt * 8 + t4 * 2;
            float2 bv = *reinterpret_cast<const float2*>(bias + col);
            float2 v0 = make_float2(acc[mt][nt][0] + bv.x, acc[mt][nt][1] + bv.y);
            float2 v1 = make_float2(acc[mt][nt][2] + bv.x, acc[mt][nt][3] + bv.y);
            if (mode == 0) {
                int h = col >> 6, d = col & 63;
                int b0 = row0 >> 11, s0 = row0 & 2047;
                *reinterpret_cast<float2*>(
                    C + (size_t)((b0 * HEADS + h) * SEQ + s0) * DK + d) = v0;
                int r1 = row0 + 8;
                int b1 = r1 >> 11, s1 = r1 & 2047;
                *reinterpret_cast<float2*>(
                    C + (size_t)((b1 * HEADS + h) * SEQ + s1) * DK + d) = v1;
            } else {
                *reinterpret_cast<float2*>(C + (size_t)row0 * DMODEL + col) = v0;
                *reinterpret_cast<float2*>(C + (size_t)(row0 + 8) * DMODEL + col) = v1;
            }
        }
    }
}

// ---------------------------------------------------------------------------
// Flash attention (fp32, known good from R2): one CTA per (bh, 64-row Q tile).
// ---------------------------------------------------------------------------
__device__ __forceinline__ float red_max16(float v) {
#pragma unroll
    for (int m = 8; m > 0; m >>= 1) v = fmaxf(v, __shfl_xor_sync(0xffffffffu, v, m));
    return v;
}
__device__ __forceinline__ float red_sum16(float v) {
#pragma unroll
    for (int m = 8; m > 0; m >>= 1) v += __shfl_xor_sync(0xffffffffu, v, m);
    return v;
}

extern __shared__ float fsmem[];

__global__ __launch_bounds__(256) void mha_attn_kernel(float* __restrict__ scores_out)
{
    float* Qs = fsmem;
    float* Ks = fsmem + 4096;
    float* Vs = fsmem + 8192;
    float* Ps = fsmem + 12288;

    const int tid = threadIdx.x;
    const int tx = tid & 15;
    const int ty = tid >> 4;
    const int q0 = blockIdx.x * 64;
    const int bh = blockIdx.y;

    const float* Qb = g_Q + (size_t)bh * SEQ * DK;
    const float* Kb = g_K + (size_t)bh * SEQ * DK;
    const float* Vb = g_V + (size_t)bh * SEQ * DK;

    const float qscale = 0.125f;

#pragma unroll
    for (int it = 0; it < 4; it++) {
        int idx = tid + it * 256;
        int r = idx >> 4;
        int d = (idx & 15) * 4;
        float4 v = *reinterpret_cast<const float4*>(Qb + (size_t)(q0 + r) * DK + d);
        Qs[(d + 0) * 64 + r] = v.x * qscale;
        Qs[(d + 1) * 64 + r] = v.y * qscale;
        Qs[(d + 2) * 64 + r] = v.z * qscale;
        Qs[(d + 3) * 64 + r] = v.w * qscale;
    }

    float m_i[4], l_i[4], o[4][4];
#pragma unroll
    for (int i = 0; i < 4; i++) {
        m_i[i] = -INFINITY; l_i[i] = 0.f;
#pragma unroll
        for (int j = 0; j < 4; j++) o[i][j] = 0.f;
    }
    __syncthreads();

    for (int kt = 0; kt < SEQ / 64; kt++) {
        const int c0 = kt * 64;
#pragma unroll
        for (int it = 0; it < 4; it++) {
            int idx = tid + it * 256;
            int r = idx >> 4;
            int d = (idx & 15) * 4;
            float4 kv = *reinterpret_cast<const float4*>(Kb + (size_t)(c0 + r) * DK + d);
            Ks[(d + 0) * 64 + r] = kv.x;
            Ks[(d + 1) * 64 + r] = kv.y;
            Ks[(d + 2) * 64 + r] = kv.z;
            Ks[(d + 3) * 64 + r] = kv.w;
            float4 vv = *reinterpret_cast<const float4*>(Vb + (size_t)(c0 + r) * DK + d);
            *reinterpret_cast<float4*>(&Vs[r * 64 + d]) = vv;
        }
        __syncthreads();

        float s[4][4];
#pragma unroll
        for (int i = 0; i < 4; i++)
#pragma unroll
            for (int j = 0; j < 4; j++) s[i][j] = 0.f;
#pragma unroll 8
        for (int d = 0; d < 64; d++) {
            float4 qv = *reinterpret_cast<const float4*>(&Qs[d * 64 + ty * 4]);
            float4 kv = *reinterpret_cast<const float4*>(&Ks[d * 64 + tx * 4]);
            float a[4] = {qv.x, qv.y, qv.z, qv.w};
            float b[4] = {kv.x, kv.y, kv.z, kv.w};
#pragma unroll
            for (int i = 0; i < 4; i++)
#pragma unroll
                for (int j = 0; j < 4; j++) s[i][j] = fmaf(a[i], b[j], s[i][j]);
        }

        float p[4][4];
#pragma unroll
        for (int i = 0; i < 4; i++) {
            float tm = fmaxf(fmaxf(s[i][0], s[i][1]), fmaxf(s[i][2], s[i][3]));
            tm = red_max16(tm);
            float m_new = fmaxf(m_i[i], tm);
            float rs = 0.f;
#pragma unroll
            for (int j = 0; j < 4; j++) { p[i][j] = __expf(s[i][j] - m_new); rs += p[i][j]; }
            rs = red_sum16(rs);
            float sc = __expf(m_i[i] - m_new);
            l_i[i] = l_i[i] * sc + rs;
            m_i[i] = m_new;
#pragma unroll
            for (int j = 0; j < 4; j++) o[i][j] *= sc;
        }
        __syncthreads();

#pragma unroll
        for (int i = 0; i < 4; i++) {
            *reinterpret_cast<float4*>(&Ps[(ty * 4 + i) * 64 + tx * 4]) =
                make_float4(p[i][0], p[i][1], p[i][2], p[i][3]);
        }
        __syncthreads();

#pragma unroll 8
        for (int j = 0; j < 64; j++) {
            float4 vv = *reinterpret_cast<const float4*>(&Vs[j * 64 + tx * 4]);
            float pv[4];
#pragma unroll
            for (int i = 0; i < 4; i++) pv[i] = Ps[(ty * 4 + i) * 64 + j];
#pragma unroll
            for (int i = 0; i < 4; i++) {
                o[i][0] = fmaf(pv[i], vv.x, o[i][0]);
                o[i][1] = fmaf(pv[i], vv.y, o[i][1]);
                o[i][2] = fmaf(pv[i], vv.z, o[i][2]);
                o[i][3] = fmaf(pv[i], vv.w, o[i][3]);
            }
        }
        __syncthreads();
    }

#pragma unroll
    for (int i = 0; i < 4; i++) {
        float inv = 1.f / l_i[i];
        int r = q0 + ty * 4 + i;
        float4 v = make_float4(o[i][0] * inv, o[i][1] * inv, o[i][2] * inv, o[i][3] * inv);
        *reinterpret_cast<float4*>(scores_out + ((size_t)bh * SEQ + r) * DK + tx * 4) = v;
    }
}

// ---------------------------------------------------------------------------
extern "C" void kernel_launch(void* const* d_in, const int* in_sizes, int n_in,
                              void* d_out, int out_size)
{
    const float* query = (const float*)d_in[0];
    const float* key   = (const float*)d_in[1];
    const float* value = (const float*)d_in[2];
    const float* Wq = (const float*)d_in[3];
    const float* bq = (const float*)d_in[4];
    const float* Wk = (const float*)d_in[5];
    const float* bk = (const float*)d_in[6];
    const float* Wv = (const float*)d_in[7];
    const float* bv = (const float*)d_in[8];
    const float* Wo = (const float*)d_in[9];
    const float* bo = (const float*)d_in[10];

    float* out    = (float*)d_out;
    float* scores = (float*)d_out + QKV_ELEMS;

    float *dQ, *dK, *dV;
    cudaGetSymbolAddress((void**)&dQ, g_Q);
    cudaGetSymbolAddress((void**)&dK, g_K);
    cudaGetSymbolAddress((void**)&dV, g_V);
    __nv_bfloat16 *ah, *al, *wh, *wl;
    cudaGetSymbolAddress((void**)&ah, g_Ah);
    cudaGetSymbolAddress((void**)&al, g_Al);
    cudaGetSymbolAddress((void**)&wh, g_Wh);
    cudaGetSymbolAddress((void**)&wl, g_Wl);

    static bool attr_set = false;
    if (!attr_set) {
        cudaFuncSetAttribute(mha_attn_kernel,
                             cudaFuncAttributeMaxDynamicSharedMemorySize, 16384 * 4);
        cudaFuncSetAttribute(gemm_mma_kernel,
                             cudaFuncAttributeMaxDynamicSharedMemorySize, GEMM_SMEM);
        attr_set = true;
    }

    const int nA4 = MROWS * DMODEL / 4;
    const int nW4 = DMODEL * DMODEL / 4;
    dim3 ggrid(DMODEL / 128, MROWS / 128);   // (8, 32)

    // Q projection
    split_kernel<<<nA4 / 256, 256>>>(query, ah, al, nA4, 0);
    split_kernel<<<nW4 / 256, 256>>>(Wq, wh, wl, nW4, 0);
    gemm_mma_kernel<<<ggrid, 256, GEMM_SMEM>>>(ah, al, wh, wl, bq, dQ, 0);
    // K projection
    split_kernel<<<nA4 / 256, 256>>>(key, ah, al, nA4, 0);
    split_kernel<<<nW4 / 256, 256>>>(Wk, wh, wl, nW4, 0);
    gemm_mma_kernel<<<ggrid, 256, GEMM_SMEM>>>(ah, al, wh, wl, bk, dK, 0);
    // V projection
    split_kernel<<<nA4 / 256, 256>>>(value, ah, al, nA4, 0);
    split_kernel<<<nW4 / 256, 256>>>(Wv, wh, wl, nW4, 0);
    gemm_mma_kernel<<<ggrid, 256, GEMM_SMEM>>>(ah, al, wh, wl, bv, dV, 0);

    // attention -> scores
    dim3 agrid(SEQ / 64, BS * HEADS);
    mha_attn_kernel<<<agrid, 256, 16384 * 4>>>(scores);

    // output projection (scores gathered/concatenated on the fly)
    split_kernel<<<nA4 / 256, 256>>>(scores, ah, al, nA4, 1);
    split_kernel<<<nW4 / 256, 256>>>(Wo, wh, wl, nW4, 0);
    gemm_mma_kernel<<<ggrid, 256, GEMM_SMEM>>>(ah, al, wh, wl, bo, out, 1);
}

// round 8
// speedup vs baseline: 2.7029x; 1.8190x over previous
#include <cuda_runtime.h>
#include <cuda_bf16.h>
#include <math.h>
#include <stdint.h>

// Problem constants
#define BS      2
#define SEQ     2048
#define DMODEL  1024
#define HEADS   16
#define DK      64
#define MROWS   (BS * SEQ)                  // 4096
#define QKV_ELEMS (BS * HEADS * SEQ * DK)   // 4,194,304

// ---------------------------------------------------------------------------
// Device scratch (allocation-free rule)
// ---------------------------------------------------------------------------
__device__ __align__(16) __nv_bfloat16 g_Qh[QKV_ELEMS];
__device__ __align__(16) __nv_bfloat16 g_Ql[QKV_ELEMS];
__device__ __align__(16) __nv_bfloat16 g_Kh[QKV_ELEMS];
__device__ __align__(16) __nv_bfloat16 g_Kl[QKV_ELEMS];
__device__ __align__(16) __nv_bfloat16 g_Vh[QKV_ELEMS];   // [bh][d][s] transposed
__device__ __align__(16) __nv_bfloat16 g_Vl[QKV_ELEMS];   // [bh][d][s] transposed
__device__ __align__(16) __nv_bfloat16 g_Ah[MROWS * DMODEL];
__device__ __align__(16) __nv_bfloat16 g_Al[MROWS * DMODEL];
__device__ __align__(16) __nv_bfloat16 g_Wh[DMODEL * DMODEL];
__device__ __align__(16) __nv_bfloat16 g_Wl[DMODEL * DMODEL];

// ---------------------------------------------------------------------------
// Helpers
// ---------------------------------------------------------------------------
__device__ __forceinline__ uint32_t smem_u32(const void* p) {
    uint32_t a;
    asm("{ .reg .u64 t; cvta.to.shared.u64 t, %1; cvt.u32.u64 %0, t; }" : "=r"(a) : "l"(p));
    return a;
}
__device__ __forceinline__ uint32_t lds32(uint32_t addr) {
    uint32_t v;
    asm volatile("ld.shared.b32 %0, [%1];" : "=r"(v) : "r"(addr));
    return v;
}
__device__ __forceinline__ void cp_async16(uint32_t saddr, const void* gaddr) {
    asm volatile("cp.async.cg.shared.global [%0], [%1], 16;" :: "r"(saddr), "l"(gaddr));
}
#define CP_COMMIT() asm volatile("cp.async.commit_group;" ::: "memory")
#define CP_WAIT(n)  asm volatile("cp.async.wait_group %0;" :: "n"(n) : "memory")

// D = A(16x16) * B(16x8) + D, bf16 inputs, fp32 accum
__device__ __forceinline__ void mma16816(float* c, const uint32_t* a, const uint32_t* b) {
    asm volatile(
        "mma.sync.aligned.m16n8k16.row.col.f32.bf16.bf16.f32 "
        "{%0,%1,%2,%3}, {%4,%5,%6,%7}, {%8,%9}, {%0,%1,%2,%3};"
        : "+f"(c[0]), "+f"(c[1]), "+f"(c[2]), "+f"(c[3])
        : "r"(a[0]), "r"(a[1]), "r"(a[2]), "r"(a[3]), "r"(b[0]), "r"(b[1]));
}
__device__ __forceinline__ uint32_t pack_bf16(float a, float b) {
    __nv_bfloat162 t = __floats2bfloat162_rn(a, b);
    return *reinterpret_cast<uint32_t*>(&t);
}
__device__ __forceinline__ void split1(float v, __nv_bfloat16& h, __nv_bfloat16& l) {
    h = __float2bfloat16(v);
    l = __float2bfloat16(v - __bfloat162float(h));
}

// ---------------------------------------------------------------------------
// fp32 -> bf16 hi/lo split (flat arrays)
// ---------------------------------------------------------------------------
__global__ __launch_bounds__(256) void split_kernel(
    const float* __restrict__ src, __nv_bfloat16* __restrict__ hi,
    __nv_bfloat16* __restrict__ lo, int n4)
{
    int i = blockIdx.x * blockDim.x + threadIdx.x;
    if (i >= n4) return;
    int e = i * 4;
    float4 f = reinterpret_cast<const float4*>(src)[i];
    __nv_bfloat16 h0, h1, h2, h3, l0, l1, l2, l3;
    split1(f.x, h0, l0); split1(f.y, h1, l1);
    split1(f.z, h2, l2); split1(f.w, h3, l3);
    uint2 hv, lv;
    hv.x = pack_bf16(f.x, f.y); hv.y = pack_bf16(f.z, f.w);  // same as packing h0..h3
    // (pack_bf16 rounds fp32->bf16 directly == h values)
    __nv_bfloat162 lp0 = __halves2bfloat162(l0, l1), lp1 = __halves2bfloat162(l2, l3);
    lv.x = *reinterpret_cast<uint32_t*>(&lp0); lv.y = *reinterpret_cast<uint32_t*>(&lp1);
    *reinterpret_cast<uint2*>(hi + e) = hv;
    *reinterpret_cast<uint2*>(lo + e) = lv;
}

// ---------------------------------------------------------------------------
// mma.sync bf16-split GEMM:  C[m,n] = sum_k A[m,k] W[n,k] + bias[n]
//   = Ah·Wh + Ah·Wl + Al·Wh
// CTA 128x128, BK=32, 256 threads, warps 2(M)x4(N), warp tile 64x32.
// mode 0: fp32 row-major -> Cf
// mode 1: bf16 hi/lo split, head-split [bh][s][d] -> Ch/Cl  (Q: scale=0.125)
// mode 2: bf16 hi/lo split, transposed [bh][d][s] -> Ch/Cl  (V)
// ---------------------------------------------------------------------------
#define SA        40
#define TILE_B    (128 * SA * 2)
#define BUF_B     (4 * TILE_B)
#define GEMM_SMEM (2 * BUF_B)

__global__ __launch_bounds__(256) void gemm_mma_kernel(
    const __nv_bfloat16* __restrict__ Ah, const __nv_bfloat16* __restrict__ Al,
    const __nv_bfloat16* __restrict__ Wh, const __nv_bfloat16* __restrict__ Wl,
    const float* __restrict__ bias, float* __restrict__ Cf,
    __nv_bfloat16* __restrict__ Ch, __nv_bfloat16* __restrict__ Cl,
    int mode, float scale)
{
    extern __shared__ __align__(128) char smem[];
    const uint32_t sb = smem_u32(smem);

    const int tid  = threadIdx.x;
    const int lane = tid & 31;
    const int wid  = tid >> 5;
    const int wm   = wid >> 2;
    const int wn   = wid & 3;
    const int g    = lane >> 2;
    const int t4   = lane & 3;

    const int m0 = blockIdx.y * 128;
    const int n0 = blockIdx.x * 128;

    const int lr0 = tid >> 2;
    const int lc0 = (tid & 3) * 8;

    float acc[4][4][4];
#pragma unroll
    for (int mt = 0; mt < 4; mt++)
#pragma unroll
        for (int nt = 0; nt < 4; nt++)
#pragma unroll
            for (int q = 0; q < 4; q++) acc[mt][nt][q] = 0.f;

    auto load_tile = [&](int buf, int k0) {
        uint32_t base = sb + buf * BUF_B;
#pragma unroll
        for (int it = 0; it < 2; it++) {
            int r = lr0 + it * 64;
            uint32_t soff = (uint32_t)(r * SA + lc0) * 2;
            size_t ga = (size_t)(m0 + r) * DMODEL + k0 + lc0;
            size_t gb = (size_t)(n0 + r) * DMODEL + k0 + lc0;
            cp_async16(base + 0 * TILE_B + soff, Ah + ga);
            cp_async16(base + 1 * TILE_B + soff, Al + ga);
            cp_async16(base + 2 * TILE_B + soff, Wh + gb);
            cp_async16(base + 3 * TILE_B + soff, Wl + gb);
        }
        CP_COMMIT();
    };

    load_tile(0, 0);

    const int NT = DMODEL / 32;
    for (int kt = 0; kt < NT; kt++) {
        const int buf = kt & 1;
        if (kt + 1 < NT) {
            load_tile(buf ^ 1, (kt + 1) * 32);
            CP_WAIT(1);
        } else {
            CP_WAIT(0);
        }
        __syncthreads();

        const uint32_t bA = sb + buf * BUF_B;
        const uint32_t bB = bA + 2 * TILE_B;

#pragma unroll
        for (int s = 0; s < 2; s++) {
            const int kc = s * 16 + t4 * 2;
            uint32_t ah[4][4], al[4][4];
#pragma unroll
            for (int mt = 0; mt < 4; mt++) {
                int row = wm * 64 + mt * 16 + g;
                uint32_t o00 = (uint32_t)(row * SA + kc) * 2;
                uint32_t o10 = o00 + 8 * SA * 2;
                ah[mt][0] = lds32(bA + o00);
                ah[mt][1] = lds32(bA + o10);
                ah[mt][2] = lds32(bA + o00 + 16);
                ah[mt][3] = lds32(bA + o10 + 16);
                al[mt][0] = lds32(bA + TILE_B + o00);
                al[mt][1] = lds32(bA + TILE_B + o10);
                al[mt][2] = lds32(bA + TILE_B + o00 + 16);
                al[mt][3] = lds32(bA + TILE_B + o10 + 16);
            }
            uint32_t bh[4][2], bl[4][2];
#pragma unroll
            for (int nt = 0; nt < 4; nt++) {
                int n = wn * 32 + nt * 8 + g;
                uint32_t o = (uint32_t)(n * SA + kc) * 2;
                bh[nt][0] = lds32(bB + o);
                bh[nt][1] = lds32(bB + o + 16);
                bl[nt][0] = lds32(bB + TILE_B + o);
                bl[nt][1] = lds32(bB + TILE_B + o + 16);
            }
#pragma unroll
            for (int mt = 0; mt < 4; mt++)
#pragma unroll
                for (int nt = 0; nt < 4; nt++) {
                    mma16816(acc[mt][nt], ah[mt], bh[nt]);
                    mma16816(acc[mt][nt], ah[mt], bl[nt]);
                    mma16816(acc[mt][nt], al[mt], bh[nt]);
                }
        }
        __syncthreads();
    }

    // epilogue
#pragma unroll
    for (int mt = 0; mt < 4; mt++) {
        int row0 = m0 + wm * 64 + mt * 16 + g;
#pragma unroll
        for (int nt = 0; nt < 4; nt++) {
            int col = n0 + wn * 32 + nt * 8 + t4 * 2;
            float2 bv = *reinterpret_cast<const float2*>(bias + col);
            float v[2][2];
            v[0][0] = (acc[mt][nt][0] + bv.x) * scale;
            v[0][1] = (acc[mt][nt][1] + bv.y) * scale;
            v[1][0] = (acc[mt][nt][2] + bv.x) * scale;
            v[1][1] = (acc[mt][nt][3] + bv.y) * scale;
            if (mode == 0) {
                *reinterpret_cast<float2*>(Cf + (size_t)row0 * DMODEL + col) =
                    make_float2(v[0][0], v[0][1]);
                *reinterpret_cast<float2*>(Cf + (size_t)(row0 + 8) * DMODEL + col) =
                    make_float2(v[1][0], v[1][1]);
            } else {
                int h = col >> 6, d = col & 63;
#pragma unroll
                for (int rr = 0; rr < 2; rr++) {
                    int row = row0 + rr * 8;
                    int b = row >> 11, s = row & 2047;
                    int bh = b * HEADS + h;
                    __nv_bfloat16 h0, h1, l0, l1;
                    split1(v[rr][0], h0, l0);
                    split1(v[rr][1], h1, l1);
                    if (mode == 1) {
                        size_t off = ((size_t)bh * SEQ + s) * DK + d;
                        __nv_bfloat162 hp = __halves2bfloat162(h0, h1);
                        __nv_bfloat162 lp = __halves2bfloat162(l0, l1);
                        *reinterpret_cast<uint32_t*>(Ch + off) =
                            *reinterpret_cast<uint32_t*>(&hp);
                        *reinterpret_cast<uint32_t*>(Cl + off) =
                            *reinterpret_cast<uint32_t*>(&lp);
                    } else {   // mode 2: V transposed [bh][d][s]
                        size_t o0 = ((size_t)bh * DK + d) * SEQ + s;
                        size_t o1 = ((size_t)bh * DK + d + 1) * SEQ + s;
                        Ch[o0] = h0; Ch[o1] = h1;
                        Cl[o0] = l0; Cl[o1] = l1;
                    }
                }
            }
        }
    }
}

// ---------------------------------------------------------------------------
// Tensor-core flash attention (3-pass bf16 split, fp32 softmax):
// CTA = 128 Q rows x (bh), 8 warps each owning 16 full rows.
// Streams 64-key chunks; Kh/Kl (keys x dk) and Vh/Vl (d x keys, pre-transposed
// in gmem) double-buffered via cp.async. Writes fp32 scores to d_out and the
// hi/lo split of scores into g_Ah/g_Al (concat layout) for the out projection.
// ---------------------------------------------------------------------------
#define ATT_SA    72                       // smem stride (bf16) for 64-wide tiles
#define ATT_TILE  (64 * ATT_SA * 2)        // 9216 B
#define ATT_BUF   (4 * ATT_TILE)           // 36864 B
#define ATT_SMEM  (2 * ATT_BUF)            // 73728 B

__global__ __launch_bounds__(256) void attn_mma_kernel(
    float* __restrict__ scores,
    __nv_bfloat16* __restrict__ Ao_h, __nv_bfloat16* __restrict__ Ao_l)
{
    extern __shared__ __align__(128) char asmem[];
    const uint32_t sb = smem_u32(asmem);

    const int tid  = threadIdx.x;
    const int lane = tid & 31;
    const int wid  = tid >> 5;
    const int g    = lane >> 2;
    const int t4   = lane & 3;

    const int bh = blockIdx.y;
    const int q0 = blockIdx.x * 128;
    const int qr = q0 + wid * 16;

    // ---- load Q fragments (once) ----
    uint32_t qh[4][4], ql[4][4];
    {
        const uint32_t* Qh32 = reinterpret_cast<const uint32_t*>(
            g_Qh + ((size_t)bh * SEQ + qr) * DK);
        const uint32_t* Ql32 = reinterpret_cast<const uint32_t*>(
            g_Ql + ((size_t)bh * SEQ + qr) * DK);
#pragma unroll
        for (int kf = 0; kf < 4; kf++) {
            int c0 = kf * 8 + t4;
            qh[kf][0] = Qh32[g * 32 + c0];
            qh[kf][1] = Qh32[(g + 8) * 32 + c0];
            qh[kf][2] = Qh32[g * 32 + c0 + 4];
            qh[kf][3] = Qh32[(g + 8) * 32 + c0 + 4];
            ql[kf][0] = Ql32[g * 32 + c0];
            ql[kf][1] = Ql32[(g + 8) * 32 + c0];
            ql[kf][2] = Ql32[g * 32 + c0 + 4];
            ql[kf][3] = Ql32[(g + 8) * 32 + c0 + 4];
        }
    }

    float o[8][4];
#pragma unroll
    for (int dt = 0; dt < 8; dt++)
#pragma unroll
        for (int q = 0; q < 4; q++) o[dt][q] = 0.f;
    float mrow[2] = {-INFINITY, -INFINITY};
    float lrow[2] = {0.f, 0.f};

    auto load_chunk = [&](int buf, int kt) {
        uint32_t base = sb + buf * ATT_BUF;
#pragma unroll
        for (int it = 0; it < 2; it++) {
            int idx = tid + it * 256;
            int row = idx >> 3, c8 = idx & 7;
            uint32_t so = (uint32_t)row * (ATT_SA * 2) + c8 * 16;
            size_t gk = ((size_t)bh * SEQ + kt * 64 + row) * DK + c8 * 8;
            cp_async16(base + so, g_Kh + gk);
            cp_async16(base + ATT_TILE + so, g_Kl + gk);
            size_t gv = ((size_t)bh * DK + row) * SEQ + kt * 64 + c8 * 8;
            cp_async16(base + 2 * ATT_TILE + so, g_Vh + gv);
            cp_async16(base + 3 * ATT_TILE + so, g_Vl + gv);
        }
        CP_COMMIT();
    };

    load_chunk(0, 0);

    const int NCH = SEQ / 64;   // 32
    for (int kt = 0; kt < NCH; kt++) {
        const int buf = kt & 1;
        if (kt + 1 < NCH) {
            load_chunk(buf ^ 1, kt + 1);
            CP_WAIT(1);
        } else {
            CP_WAIT(0);
        }
        __syncthreads();

        const uint32_t bK  = sb + buf * ATT_BUF;
        const uint32_t bKl = bK + ATT_TILE;
        const uint32_t bV  = bK + 2 * ATT_TILE;
        const uint32_t bVl = bK + 3 * ATT_TILE;

        // ---- S = Q K^T (3-pass) ----
        float s[8][4];
#pragma unroll
        for (int nt = 0; nt < 8; nt++)
#pragma unroll
            for (int q = 0; q < 4; q++) s[nt][q] = 0.f;
#pragma unroll
        for (int kf = 0; kf < 4; kf++) {
#pragma unroll
            for (int nt = 0; nt < 8; nt++) {
                uint32_t off = ((uint32_t)(nt * 8 + g) * ATT_SA + kf * 16 + t4 * 2) * 2;
                uint32_t kbh[2] = { lds32(bK + off),  lds32(bK + off + 16) };
                uint32_t kbl[2] = { lds32(bKl + off), lds32(bKl + off + 16) };
                mma16816(s[nt], qh[kf], kbh);
                mma16816(s[nt], qh[kf], kbl);
                mma16816(s[nt], ql[kf], kbh);
            }
        }

        // ---- online softmax (rows g and g+8) ----
#pragma unroll
        for (int hh = 0; hh < 2; hh++) {
            float mx = -INFINITY;
#pragma unroll
            for (int nt = 0; nt < 8; nt++)
                mx = fmaxf(mx, fmaxf(s[nt][2 * hh], s[nt][2 * hh + 1]));
            mx = fmaxf(mx, __shfl_xor_sync(0xffffffffu, mx, 1));
            mx = fmaxf(mx, __shfl_xor_sync(0xffffffffu, mx, 2));
            float mnew = fmaxf(mrow[hh], mx);
            float sc = __expf(mrow[hh] - mnew);
            mrow[hh] = mnew;
            float rs = 0.f;
#pragma unroll
            for (int nt = 0; nt < 8; nt++) {
                s[nt][2 * hh]     = __expf(s[nt][2 * hh] - mnew);
                s[nt][2 * hh + 1] = __expf(s[nt][2 * hh + 1] - mnew);
                rs += s[nt][2 * hh] + s[nt][2 * hh + 1];
            }
            rs += __shfl_xor_sync(0xffffffffu, rs, 1);
            rs += __shfl_xor_sync(0xffffffffu, rs, 2);
            lrow[hh] = lrow[hh] * sc + rs;
#pragma unroll
            for (int dt = 0; dt < 8; dt++) {
                o[dt][2 * hh]     *= sc;
                o[dt][2 * hh + 1] *= sc;
            }
        }

        // ---- pack P into A fragments (hi/lo) ----
        uint32_t ph[4][4], pl[4][4];
#pragma unroll
        for (int kf = 0; kf < 4; kf++) {
#pragma unroll
            for (int half = 0; half < 2; half++) {      // tile 2kf+half
                const float* sv = s[2 * kf + half];
                __nv_bfloat16 h0, h1, h2, h3, l0, l1, l2, l3;
                split1(sv[0], h0, l0); split1(sv[1], h1, l1);
                split1(sv[2], h2, l2); split1(sv[3], h3, l3);
                __nv_bfloat162 a, b, c, d;
                a = __halves2bfloat162(h0, h1); b = __halves2bfloat162(h2, h3);
                c = __halves2bfloat162(l0, l1); d = __halves2bfloat162(l2, l3);
                ph[kf][2 * half + 0] = *reinterpret_cast<uint32_t*>(&a);
                ph[kf][2 * half + 1] = *reinterpret_cast<uint32_t*>(&b);
                pl[kf][2 * half + 0] = *reinterpret_cast<uint32_t*>(&c);
                pl[kf][2 * half + 1] = *reinterpret_cast<uint32_t*>(&d);
            }
        }

        // ---- O += P V (3-pass) ----
#pragma unroll
        for (int kf = 0; kf < 4; kf++) {
#pragma unroll
            for (int dt = 0; dt < 8; dt++) {
                uint32_t off = ((uint32_t)(dt * 8 + g) * ATT_SA + kf * 16 + t4 * 2) * 2;
                uint32_t vbh[2] = { lds32(bV + off),  lds32(bV + off + 16) };
                uint32_t vbl[2] = { lds32(bVl + off), lds32(bVl + off + 16) };
                mma16816(o[dt], ph[kf], vbh);
                mma16816(o[dt], ph[kf], vbl);
                mma16816(o[dt], pl[kf], vbh);
            }
        }
        __syncthreads();
    }

    // ---- epilogue: normalize, write scores fp32 + hi/lo split into Ao ----
    const int b = bh >> 4, hhd = bh & 15;
#pragma unroll
    for (int hh = 0; hh < 2; hh++) {
        float inv = 1.f / lrow[hh];
        int srow = qr + g + hh * 8;
#pragma unroll
        for (int dt = 0; dt < 8; dt++) {
            int d = dt * 8 + t4 * 2;
            float v0 = o[dt][2 * hh] * inv;
            float v1 = o[dt][2 * hh + 1] * inv;
            *reinterpret_cast<float2*>(
                scores + ((size_t)bh * SEQ + srow) * DK + d) = make_float2(v0, v1);
            __nv_bfloat16 h0, h1, l0, l1;
            split1(v0, h0, l0); split1(v1, h1, l1);
            __nv_bfloat162 hp = __halves2bfloat162(h0, h1);
            __nv_bfloat162 lp = __halves2bfloat162(l0, l1);
            size_t mi = ((size_t)(b * SEQ + srow)) * DMODEL + hhd * DK + d;
            *reinterpret_cast<uint32_t*>(Ao_h + mi) = *reinterpret_cast<uint32_t*>(&hp);
            *reinterpret_cast<uint32_t*>(Ao_l + mi) = *reinterpret_cast<uint32_t*>(&lp);
        }
    }
}

// ---------------------------------------------------------------------------
extern "C" void kernel_launch(void* const* d_in, const int* in_sizes, int n_in,
                              void* d_out, int out_size)
{
    const float* query = (const float*)d_in[0];
    const float* key   = (const float*)d_in[1];
    const float* value = (const float*)d_in[2];
    const float* Wq = (const float*)d_in[3];
    const float* bq = (const float*)d_in[4];
    const float* Wk = (const float*)d_in[5];
    const float* bk = (const float*)d_in[6];
    const float* Wv = (const float*)d_in[7];
    const float* bv = (const float*)d_in[8];
    const float* Wo = (const float*)d_in[9];
    const float* bo = (const float*)d_in[10];

    float* out    = (float*)d_out;
    float* scores = (float*)d_out + QKV_ELEMS;

    __nv_bfloat16 *qh, *ql, *kh, *kl, *vh, *vl, *ah, *al, *wh, *wl;
    cudaGetSymbolAddress((void**)&qh, g_Qh);
    cudaGetSymbolAddress((void**)&ql, g_Ql);
    cudaGetSymbolAddress((void**)&kh, g_Kh);
    cudaGetSymbolAddress((void**)&kl, g_Kl);
    cudaGetSymbolAddress((void**)&vh, g_Vh);
    cudaGetSymbolAddress((void**)&vl, g_Vl);
    cudaGetSymbolAddress((void**)&ah, g_Ah);
    cudaGetSymbolAddress((void**)&al, g_Al);
    cudaGetSymbolAddress((void**)&wh, g_Wh);
    cudaGetSymbolAddress((void**)&wl, g_Wl);

    static bool attr_set = false;
    if (!attr_set) {
        cudaFuncSetAttribute(gemm_mma_kernel,
                             cudaFuncAttributeMaxDynamicSharedMemorySize, GEMM_SMEM);
        cudaFuncSetAttribute(attn_mma_kernel,
                             cudaFuncAttributeMaxDynamicSharedMemorySize, ATT_SMEM);
        attr_set = true;
    }

    const int nA4 = MROWS * DMODEL / 4;
    const int nW4 = DMODEL * DMODEL / 4;
    dim3 ggrid(DMODEL / 128, MROWS / 128);   // (8, 32)

    // Q projection (pre-scaled by 1/sqrt(dk) = 0.125)
    split_kernel<<<nA4 / 256, 256>>>(query, ah, al, nA4);
    split_kernel<<<nW4 / 256, 256>>>(Wq, wh, wl, nW4);
    gemm_mma_kernel<<<ggrid, 256, GEMM_SMEM>>>(ah, al, wh, wl, bq,
                                               nullptr, qh, ql, 1, 0.125f);
    // K projection
    split_kernel<<<nA4 / 256, 256>>>(key, ah, al, nA4);
    split_kernel<<<nW4 / 256, 256>>>(Wk, wh, wl, nW4);
    gemm_mma_kernel<<<ggrid, 256, GEMM_SMEM>>>(ah, al, wh, wl, bk,
                                               nullptr, kh, kl, 1, 1.0f);
    // V projection (writes transposed [bh][d][s])
    split_kernel<<<nA4 / 256, 256>>>(value, ah, al, nA4);
    split_kernel<<<nW4 / 256, 256>>>(Wv, wh, wl, nW4);
    gemm_mma_kernel<<<ggrid, 256, GEMM_SMEM>>>(ah, al, wh, wl, bv,
                                               nullptr, vh, vl, 2, 1.0f);

    // Wo split (needs g_Wh free after V gemm)
    split_kernel<<<nW4 / 256, 256>>>(Wo, wh, wl, nW4);

    // attention: scores fp32 -> d_out, hi/lo split -> g_Ah/g_Al
    dim3 agrid(SEQ / 128, BS * HEADS);       // (16, 32)
    attn_mma_kernel<<<agrid, 256, ATT_SMEM>>>(scores, ah, al);

    // output projection
    gemm_mma_kernel<<<ggrid, 256, GEMM_SMEM>>>(ah, al, wh, wl, bo,
                                               out, nullptr, nullptr, 0, 1.0f);
}